// round 14
// baseline (speedup 1.0000x reference)
#include <cuda_runtime.h>
#include <cuda_bf16.h>
#include <cstdint>

// ---------------------------------------------------------------------------
// MultiHeadRegionalAttention2D — R12 (= R10 resubmit #2): HMMA proj + fused qk->g
//   x:[1,128,192,192]  wq,wk,wv:[256,128]  out:[1,256,192,192]
//
//   qkv = W x  via 3-term bf16 split: whi*xhi + wlo*xhi + whi*xlo  (fp32 acc)
//   g[head,p]  = (sum_{c in head} q[c,p]*k[c,p]) / 16
//   score_s(p) = softmax over 9 slots of g[head, p+delta_s]  (OOB logit = 0)
//   out[c,p]   = sum_s score_s * v[c, p+delta_s]             (OOB v = 0)
//
// Weight rows reordered so each qk m-tile = [q_h|k_h|q_h'|k_h'] (32 rows each);
// q/k fragments then live in adjacent warps with identical layouts -> g is
// computed in the MMA epilogue (smem exchange + shfl reduce). q,k never hit
// DRAM; g_kernel is gone.
// ---------------------------------------------------------------------------

#define C_IN   128
#define HDIM   192
#define NPIX   (192*192)          // 36864
#define NHEAD  8
#define SPAD   72                 // smem row stride in bf16 (conflict-free ldmatrix)
#define XPAD   72                 // exchange row stride in f32

__device__ float          d_v [256 * NPIX];
__device__ float          d_g [NHEAD * NPIX];
__device__ __nv_bfloat16  d_whi[768 * 128];           // [m][k], reordered rows
__device__ __nv_bfloat16  d_wlo[768 * 128];
__device__ __nv_bfloat16  d_xhi[(size_t)NPIX * 128];  // [px][k]
__device__ __nv_bfloat16  d_xlo[(size_t)NPIX * 128];

typedef unsigned int u32;

__device__ __forceinline__ u32 s2u(const void* p) {
    return (u32)__cvta_generic_to_shared(p);
}
__device__ __forceinline__ void ldm4(u32* r, u32 addr) {
    asm volatile("ldmatrix.sync.aligned.m8n8.x4.shared.b16 {%0,%1,%2,%3}, [%4];"
                 : "=r"(r[0]), "=r"(r[1]), "=r"(r[2]), "=r"(r[3]) : "r"(addr));
}
__device__ __forceinline__ void mma16816(float* c, const u32* a, const u32* b) {
    asm volatile(
        "mma.sync.aligned.m16n8k16.row.col.f32.bf16.bf16.f32 "
        "{%0,%1,%2,%3}, {%4,%5,%6,%7}, {%8,%9}, {%0,%1,%2,%3};"
        : "+f"(c[0]), "+f"(c[1]), "+f"(c[2]), "+f"(c[3])
        : "r"(a[0]), "r"(a[1]), "r"(a[2]), "r"(a[3]), "r"(b[0]), "r"(b[1]));
}

// ---------------------------------------------------------------------------
// Kernel A: split + REORDER weights -> bf16 hi/lo, row-major [nm][k].
//   nm <  512: qk tiles. tile h2 = nm>>7 covers heads 2*h2, 2*h2+1 as
//              [q_h | k_h | q_h' | k_h'] (32 rows each).
//   nm >= 512: v rows (nm-512) from wv.
// ---------------------------------------------------------------------------
__global__ __launch_bounds__(256) void wsplit_kernel(
    const float* __restrict__ wq, const float* __restrict__ wk,
    const float* __restrict__ wv)
{
    int id = blockIdx.x * 256 + threadIdx.x;   // 0..98303 = nm*128+k
    int nm = id >> 7;
    int k  = id & 127;
    float v;
    if (nm < 512) {
        int h2    = nm >> 7;
        int sub   = nm & 127;
        int group = sub >> 5;               // 0=q,1=k (head 2h2); 2=q,3=k (head 2h2+1)
        int ch    = sub & 31;
        int head  = h2 * 2 + (group >> 1);
        int row   = head * 32 + ch;
        v = (group & 1) ? wk[row * C_IN + k] : wq[row * C_IN + k];
    } else {
        v = wv[(nm - 512) * C_IN + k];
    }
    __nv_bfloat16 h = __float2bfloat16(v);
    d_whi[id] = h;
    d_wlo[id] = __float2bfloat16(v - __bfloat162float(h));
}

// ---------------------------------------------------------------------------
// Kernel B: transpose + split x -> d_xhi/d_xlo [px][128] bf16
// ---------------------------------------------------------------------------
__global__ __launch_bounds__(256) void xsplit_kernel(const float* __restrict__ x)
{
    __shared__ float ts[128][33];
    const int pxBase = blockIdx.x * 32;
    const int t = threadIdx.x;
    #pragma unroll
    for (int i = 0; i < 16; i++) {
        int idx = t + i * 256;
        int k  = idx >> 5;
        int px = idx & 31;
        ts[k][px] = x[(size_t)k * NPIX + pxBase + px];
    }
    __syncthreads();
    const int px = t >> 3;
    const int c  = (t & 7) * 16;
    __nv_bfloat16 hi[16], lo[16];
    #pragma unroll
    for (int j = 0; j < 16; j++) {
        float v = ts[c + j][px];
        __nv_bfloat16 h = __float2bfloat16(v);
        hi[j] = h;
        lo[j] = __float2bfloat16(v - __bfloat162float(h));
    }
    size_t base = (size_t)(pxBase + px) * 128 + c;
    *(uint4*)(d_xhi + base)     = ((const uint4*)hi)[0];
    *(uint4*)(d_xhi + base + 8) = ((const uint4*)hi)[1];
    *(uint4*)(d_xlo + base)     = ((const uint4*)lo)[0];
    *(uint4*)(d_xlo + base + 8) = ((const uint4*)lo)[1];
}

// ---------------------------------------------------------------------------
// Kernel C: HMMA GEMM + fused qk->g epilogue.
// CTA: M=128 x N=128px, 8 warps, warp tile 32m x 64px (wm = w>>1, wn = w&1).
// blockIdx.y 0..3: qk tiles (heads 2y, 2y+1)  -> d_g only
// blockIdx.y 4..5: v tiles (v rows (y-4)*128) -> d_v
// ---------------------------------------------------------------------------
__global__ __launch_bounds__(256) void mma_proj_kernel()
{
    __shared__ __align__(16) unsigned char sraw[2 * 128 * SPAD * 2];  // 36 KB
    __nv_bfloat16* smA = (__nv_bfloat16*)sraw;
    __nv_bfloat16* smB = (__nv_bfloat16*)(sraw + 128 * SPAD * 2);
    float*         exch = (float*)sraw;            // epilogue reuse: 4 x [32][XPAD]

    const int t    = threadIdx.x;
    const int lane = t & 31;
    const int w    = t >> 5;
    const int wm   = w >> 1;          // 0..3
    const int wn   = w & 1;           // 0..1
    const int pxBase = blockIdx.x * 128;
    const int y      = blockIdx.y;
    const int mBase  = y * 128;

    float acc[2][8][4] = {};

    const int pA[6] = {0, 1, 0, 1, 0, 0};
    const int pB[6] = {0, 0, 0, 0, 1, 1};
    const int pK[6] = {0, 0, 64, 64, 0, 64};

    const int rowL = t >> 3;
    const int c8   = t & 7;

    for (int piece = 0; piece < 6; piece++) {
        if (piece > 0) __syncthreads();
        const __nv_bfloat16* As = (pA[piece] ? d_wlo : d_whi);
        const __nv_bfloat16* Bs = (pB[piece] ? d_xlo : d_xhi);
        const int kOff = pK[piece];
        #pragma unroll
        for (int i = 0; i < 4; i++) {
            int row = rowL + i * 32;
            *(uint4*)(smA + row * SPAD + c8 * 8) =
                *((const uint4*)(As + (size_t)(mBase + row) * 128 + kOff) + c8);
            *(uint4*)(smB + row * SPAD + c8 * 8) =
                *((const uint4*)(Bs + (size_t)(pxBase + row) * 128 + kOff) + c8);
        }
        __syncthreads();

        const int lr = lane & 15;
        const int lh = (lane >> 4) * 8;
        #pragma unroll
        for (int kk = 0; kk < 4; kk++) {
            u32 a[2][4];
            #pragma unroll
            for (int mf = 0; mf < 2; mf++)
                ldm4(a[mf], s2u(smA + (wm * 32 + mf * 16 + lr) * SPAD + kk * 16 + lh));
            u32 b[8][2];
            #pragma unroll
            for (int nf2 = 0; nf2 < 4; nf2++) {
                u32 r[4];
                ldm4(r, s2u(smB + (wn * 64 + nf2 * 16 + lr) * SPAD + kk * 16 + lh));
                b[nf2 * 2][0]     = r[0];
                b[nf2 * 2][1]     = r[2];
                b[nf2 * 2 + 1][0] = r[1];
                b[nf2 * 2 + 1][1] = r[3];
            }
            #pragma unroll
            for (int mf = 0; mf < 2; mf++)
                #pragma unroll
                for (int nf = 0; nf < 8; nf++)
                    mma16816(acc[mf][nf], a[mf], b[nf]);
        }
    }

    const int rQ = lane >> 2;         // 0..7
    const int cQ = (lane & 3) * 2;    // 0,2,4,6

    if (y >= 4) {
        // ---- v epilogue: write to d_v ----
        const int vBase = (y - 4) * 128;
        #pragma unroll
        for (int mf = 0; mf < 2; mf++) {
            #pragma unroll
            for (int nf = 0; nf < 8; nf++) {
                int row = vBase + wm * 32 + mf * 16 + rQ;
                int col = pxBase + wn * 64 + nf * 8 + cQ;
                *(float2*)(d_v + (size_t)row * NPIX + col) =
                    make_float2(acc[mf][nf][0], acc[mf][nf][1]);
                *(float2*)(d_v + (size_t)(row + 8) * NPIX + col) =
                    make_float2(acc[mf][nf][2], acc[mf][nf][3]);
            }
        }
        return;
    }

    // ---- qk epilogue: fused g ----
    __syncthreads();                  // mainloop smem reads complete before reuse
    const int hp = wm >> 1;           // head pair slot: 0 or 1
    float* reg = exch + (hp * 2 + wn) * (32 * XPAD);

    if ((wm & 1) == 0) {
        // q warp: spill fragments as [channel][px] (channel = local row 0..31)
        #pragma unroll
        for (int mf = 0; mf < 2; mf++) {
            #pragma unroll
            for (int nf = 0; nf < 8; nf++) {
                int row = mf * 16 + rQ;
                int col = nf * 8 + cQ;
                *(float2*)(reg + row * XPAD + col) =
                    make_float2(acc[mf][nf][0], acc[mf][nf][1]);
                *(float2*)(reg + (row + 8) * XPAD + col) =
                    make_float2(acc[mf][nf][2], acc[mf][nf][3]);
            }
        }
    }
    __syncthreads();
    if (wm & 1) {
        // k warp: product with q, reduce 32 channels
        float ps[8][2];
        #pragma unroll
        for (int nf = 0; nf < 8; nf++) { ps[nf][0] = 0.f; ps[nf][1] = 0.f; }
        #pragma unroll
        for (int mf = 0; mf < 2; mf++) {
            #pragma unroll
            for (int nf = 0; nf < 8; nf++) {
                int row = mf * 16 + rQ;
                int col = nf * 8 + cQ;
                float2 q0 = *(const float2*)(reg + row * XPAD + col);
                float2 q1 = *(const float2*)(reg + (row + 8) * XPAD + col);
                ps[nf][0] += q0.x * acc[mf][nf][0] + q1.x * acc[mf][nf][2];
                ps[nf][1] += q0.y * acc[mf][nf][1] + q1.y * acc[mf][nf][3];
            }
        }
        #pragma unroll
        for (int nf = 0; nf < 8; nf++) {
            #pragma unroll
            for (int j = 0; j < 2; j++) {
                float v = ps[nf][j];
                v += __shfl_xor_sync(0xFFFFFFFFu, v, 4);
                v += __shfl_xor_sync(0xFFFFFFFFu, v, 8);
                v += __shfl_xor_sync(0xFFFFFFFFu, v, 16);
                ps[nf][j] = v;
            }
        }
        if (lane < 4) {
            const int head = y * 2 + hp;
            float* gp = d_g + (size_t)head * NPIX + pxBase + wn * 64;
            #pragma unroll
            for (int nf = 0; nf < 8; nf++) {
                *(float2*)(gp + nf * 8 + lane * 2) =
                    make_float2(ps[nf][0] * (1.0f / 16.0f),
                                ps[nf][1] * (1.0f / 16.0f));
            }
        }
    }
}

// ---------------------------------------------------------------------------
// Kernel E: softmax + weighted gather (R8 proven).
// 256 threads = 64 pixel-quads x 4 channel-groups (8 channels each).
// ---------------------------------------------------------------------------
__global__ __launch_bounds__(256) void attn_kernel(float* __restrict__ out)
{
    const int t    = threadIdx.x;
    const int cg   = t >> 6;
    const int quad = blockIdx.x * 64 + (t & 63);
    const int hd   = blockIdx.y;
    const int p4   = quad * 4;
    const int yy0  = p4 / HDIM;
    const int x4   = p4 - yy0 * HDIM;

    bool rok[3];
    int  roff[3];
    const bool lok  = (x4 > 0);
    const bool rokc = (x4 + 4 < HDIM);

    float win[3][6];
    #pragma unroll
    for (int r = 0; r < 3; r++) {
        int yy = yy0 + r - 1;
        rok[r]  = ((unsigned)yy < (unsigned)HDIM);
        roff[r] = yy * HDIM + x4;
        if (rok[r]) {
            const float* gp = d_g + (size_t)hd * NPIX + roff[r];
            win[r][0] = lok ? gp[-1] : 0.f;
            float4 m4 = *(const float4*)gp;
            win[r][1] = m4.x; win[r][2] = m4.y; win[r][3] = m4.z; win[r][4] = m4.w;
            win[r][5] = rokc ? gp[4] : 0.f;
        } else {
            #pragma unroll
            for (int i = 0; i < 6; i++) win[r][i] = 0.f;
        }
    }

    float wt[9][4];
    #pragma unroll
    for (int px = 0; px < 4; px++) {
        float l[9];
        float m = -1e30f;
        #pragma unroll
        for (int r = 0; r < 3; r++)
            #pragma unroll
            for (int j = 0; j < 3; j++) {
                float v = win[r][px + j];
                l[r * 3 + j] = v;
                m = fmaxf(m, v);
            }
        float z = 0.f;
        #pragma unroll
        for (int s = 0; s < 9; s++) {
            float e = __expf(l[s] - m);
            wt[s][px] = e;
            z += e;
        }
        float inv = __fdividef(1.f, z);
        #pragma unroll
        for (int s = 0; s < 9; s++) wt[s][px] *= inv;
    }

    const float* vbase = d_v + (size_t)(hd * 32 + cg * 8) * NPIX;
    float* obase       = out + (size_t)(hd * 32 + cg * 8) * NPIX;

    #pragma unroll
    for (int c = 0; c < 8; c++) {
        const float* vr = vbase + (size_t)c * NPIX;
        float a0 = 0.f, a1 = 0.f, a2 = 0.f, a3 = 0.f;
        #pragma unroll
        for (int r = 0; r < 3; r++) {
            float vw[6];
            if (rok[r]) {
                const float* vp = vr + roff[r];
                vw[0] = lok ? vp[-1] : 0.f;
                float4 m4 = *(const float4*)vp;
                vw[1] = m4.x; vw[2] = m4.y; vw[3] = m4.z; vw[4] = m4.w;
                vw[5] = rokc ? vp[4] : 0.f;
            } else {
                #pragma unroll
                for (int i = 0; i < 6; i++) vw[i] = 0.f;
            }
            #pragma unroll
            for (int j = 0; j < 3; j++) {
                const int s = r * 3 + j;
                a0 += wt[s][0] * vw[0 + j];
                a1 += wt[s][1] * vw[1 + j];
                a2 += wt[s][2] * vw[2 + j];
                a3 += wt[s][3] * vw[3 + j];
            }
        }
        *(float4*)(obase + (size_t)c * NPIX + p4) = make_float4(a0, a1, a2, a3);
    }
}

// ---------------------------------------------------------------------------
extern "C" void kernel_launch(void* const* d_in, const int* in_sizes, int n_in,
                              void* d_out, int out_size)
{
    const float* x  = (const float*)d_in[0];
    const float* wq = (const float*)d_in[1];
    const float* wk = (const float*)d_in[2];
    const float* wv = (const float*)d_in[3];
    float* out = (float*)d_out;

    wsplit_kernel<<<768 * C_IN / 256, 256>>>(wq, wk, wv);
    xsplit_kernel<<<NPIX / 32, 256>>>(x);
    mma_proj_kernel<<<dim3(NPIX / 128, 6), 256>>>();
    attn_kernel<<<dim3(NPIX / 4 / 64, NHEAD), 256>>>(out);
}

// round 15
// speedup vs baseline: 1.6657x; 1.6657x over previous
#include <cuda_runtime.h>
#include <cuda_bf16.h>
#include <cstdint>

// ---------------------------------------------------------------------------
// MultiHeadRegionalAttention2D — R15: R12 fused qk->g + __launch_bounds__(256,2)
//   x:[1,128,192,192]  wq,wk,wv:[256,128]  out:[1,256,192,192]
//
//   qkv = W x  via 3-term bf16 split: whi*xhi + wlo*xhi + whi*xlo  (fp32 acc)
//   g[head,p]  = (sum_{c in head} q[c,p]*k[c,p]) / 16
//   score_s(p) = softmax over 9 slots of g[head, p+delta_s]  (OOB logit = 0)
//   out[c,p]   = sum_s score_s * v[c, p+delta_s]             (OOB v = 0)
//
// R14 regression diagnosis: fused epilogue pushed regs past 128 ->
// occupancy fell 2->1 CTA/SM -> mainloop load latency exposed (+45us).
// Fix: force min 2 blocks/SM so ptxas caps at 128 regs (cold-path spills only).
// ---------------------------------------------------------------------------

#define C_IN   128
#define HDIM   192
#define NPIX   (192*192)          // 36864
#define NHEAD  8
#define SPAD   72                 // smem row stride in bf16 (conflict-free ldmatrix)
#define XPAD   72                 // exchange row stride in f32

__device__ float          d_v [256 * NPIX];
__device__ float          d_g [NHEAD * NPIX];
__device__ __nv_bfloat16  d_whi[768 * 128];           // [m][k], reordered rows
__device__ __nv_bfloat16  d_wlo[768 * 128];
__device__ __nv_bfloat16  d_xhi[(size_t)NPIX * 128];  // [px][k]
__device__ __nv_bfloat16  d_xlo[(size_t)NPIX * 128];

typedef unsigned int u32;

__device__ __forceinline__ u32 s2u(const void* p) {
    return (u32)__cvta_generic_to_shared(p);
}
__device__ __forceinline__ void ldm4(u32* r, u32 addr) {
    asm volatile("ldmatrix.sync.aligned.m8n8.x4.shared.b16 {%0,%1,%2,%3}, [%4];"
                 : "=r"(r[0]), "=r"(r[1]), "=r"(r[2]), "=r"(r[3]) : "r"(addr));
}
__device__ __forceinline__ void mma16816(float* c, const u32* a, const u32* b) {
    asm volatile(
        "mma.sync.aligned.m16n8k16.row.col.f32.bf16.bf16.f32 "
        "{%0,%1,%2,%3}, {%4,%5,%6,%7}, {%8,%9}, {%0,%1,%2,%3};"
        : "+f"(c[0]), "+f"(c[1]), "+f"(c[2]), "+f"(c[3])
        : "r"(a[0]), "r"(a[1]), "r"(a[2]), "r"(a[3]), "r"(b[0]), "r"(b[1]));
}

// ---------------------------------------------------------------------------
// Kernel A: split + REORDER weights -> bf16 hi/lo, row-major [nm][k].
//   nm <  512: qk tiles. tile h2 = nm>>7 covers heads 2*h2, 2*h2+1 as
//              [q_h | k_h | q_h' | k_h'] (32 rows each).
//   nm >= 512: v rows (nm-512) from wv.
// ---------------------------------------------------------------------------
__global__ __launch_bounds__(256) void wsplit_kernel(
    const float* __restrict__ wq, const float* __restrict__ wk,
    const float* __restrict__ wv)
{
    int id = blockIdx.x * 256 + threadIdx.x;   // 0..98303 = nm*128+k
    int nm = id >> 7;
    int k  = id & 127;
    float v;
    if (nm < 512) {
        int h2    = nm >> 7;
        int sub   = nm & 127;
        int group = sub >> 5;               // 0=q,1=k (head 2h2); 2=q,3=k (head 2h2+1)
        int ch    = sub & 31;
        int head  = h2 * 2 + (group >> 1);
        int row   = head * 32 + ch;
        v = (group & 1) ? wk[row * C_IN + k] : wq[row * C_IN + k];
    } else {
        v = wv[(nm - 512) * C_IN + k];
    }
    __nv_bfloat16 h = __float2bfloat16(v);
    d_whi[id] = h;
    d_wlo[id] = __float2bfloat16(v - __bfloat162float(h));
}

// ---------------------------------------------------------------------------
// Kernel B: transpose + split x -> d_xhi/d_xlo [px][128] bf16
// ---------------------------------------------------------------------------
__global__ __launch_bounds__(256) void xsplit_kernel(const float* __restrict__ x)
{
    __shared__ float ts[128][33];
    const int pxBase = blockIdx.x * 32;
    const int t = threadIdx.x;
    #pragma unroll
    for (int i = 0; i < 16; i++) {
        int idx = t + i * 256;
        int k  = idx >> 5;
        int px = idx & 31;
        ts[k][px] = x[(size_t)k * NPIX + pxBase + px];
    }
    __syncthreads();
    const int px = t >> 3;
    const int c  = (t & 7) * 16;
    __nv_bfloat16 hi[16], lo[16];
    #pragma unroll
    for (int j = 0; j < 16; j++) {
        float v = ts[c + j][px];
        __nv_bfloat16 h = __float2bfloat16(v);
        hi[j] = h;
        lo[j] = __float2bfloat16(v - __bfloat162float(h));
    }
    size_t base = (size_t)(pxBase + px) * 128 + c;
    *(uint4*)(d_xhi + base)     = ((const uint4*)hi)[0];
    *(uint4*)(d_xhi + base + 8) = ((const uint4*)hi)[1];
    *(uint4*)(d_xlo + base)     = ((const uint4*)lo)[0];
    *(uint4*)(d_xlo + base + 8) = ((const uint4*)lo)[1];
}

// ---------------------------------------------------------------------------
// Kernel C: HMMA GEMM + fused qk->g epilogue.
// CTA: M=128 x N=128px, 8 warps, warp tile 32m x 64px (wm = w>>1, wn = w&1).
// blockIdx.y 0..3: qk tiles (heads 2y, 2y+1)  -> d_g only
// blockIdx.y 4..5: v tiles (v rows (y-4)*128) -> d_v
// __launch_bounds__(256, 2): cap regs at 128 so 2 CTAs/SM co-reside and the
// non-double-buffered mainloop's load latency stays hidden.
// ---------------------------------------------------------------------------
__global__ __launch_bounds__(256, 2) void mma_proj_kernel()
{
    __shared__ __align__(16) unsigned char sraw[2 * 128 * SPAD * 2];  // 36 KB
    __nv_bfloat16* smA = (__nv_bfloat16*)sraw;
    __nv_bfloat16* smB = (__nv_bfloat16*)(sraw + 128 * SPAD * 2);
    float*         exch = (float*)sraw;            // epilogue reuse: 4 x [32][XPAD]

    const int t    = threadIdx.x;
    const int lane = t & 31;
    const int w    = t >> 5;
    const int wm   = w >> 1;          // 0..3
    const int wn   = w & 1;           // 0..1
    const int pxBase = blockIdx.x * 128;
    const int y      = blockIdx.y;
    const int mBase  = y * 128;

    float acc[2][8][4] = {};

    const int pA[6] = {0, 1, 0, 1, 0, 0};
    const int pB[6] = {0, 0, 0, 0, 1, 1};
    const int pK[6] = {0, 0, 64, 64, 0, 64};

    const int rowL = t >> 3;
    const int c8   = t & 7;

    for (int piece = 0; piece < 6; piece++) {
        if (piece > 0) __syncthreads();
        const __nv_bfloat16* As = (pA[piece] ? d_wlo : d_whi);
        const __nv_bfloat16* Bs = (pB[piece] ? d_xlo : d_xhi);
        const int kOff = pK[piece];
        #pragma unroll
        for (int i = 0; i < 4; i++) {
            int row = rowL + i * 32;
            *(uint4*)(smA + row * SPAD + c8 * 8) =
                *((const uint4*)(As + (size_t)(mBase + row) * 128 + kOff) + c8);
            *(uint4*)(smB + row * SPAD + c8 * 8) =
                *((const uint4*)(Bs + (size_t)(pxBase + row) * 128 + kOff) + c8);
        }
        __syncthreads();

        const int lr = lane & 15;
        const int lh = (lane >> 4) * 8;
        #pragma unroll
        for (int kk = 0; kk < 4; kk++) {
            u32 a[2][4];
            #pragma unroll
            for (int mf = 0; mf < 2; mf++)
                ldm4(a[mf], s2u(smA + (wm * 32 + mf * 16 + lr) * SPAD + kk * 16 + lh));
            u32 b[8][2];
            #pragma unroll
            for (int nf2 = 0; nf2 < 4; nf2++) {
                u32 r[4];
                ldm4(r, s2u(smB + (wn * 64 + nf2 * 16 + lr) * SPAD + kk * 16 + lh));
                b[nf2 * 2][0]     = r[0];
                b[nf2 * 2][1]     = r[2];
                b[nf2 * 2 + 1][0] = r[1];
                b[nf2 * 2 + 1][1] = r[3];
            }
            #pragma unroll
            for (int mf = 0; mf < 2; mf++)
                #pragma unroll
                for (int nf = 0; nf < 8; nf++)
                    mma16816(acc[mf][nf], a[mf], b[nf]);
        }
    }

    const int rQ = lane >> 2;         // 0..7
    const int cQ = (lane & 3) * 2;    // 0,2,4,6

    if (y >= 4) {
        // ---- v epilogue: write to d_v ----
        const int vBase = (y - 4) * 128;
        #pragma unroll
        for (int mf = 0; mf < 2; mf++) {
            #pragma unroll
            for (int nf = 0; nf < 8; nf++) {
                int row = vBase + wm * 32 + mf * 16 + rQ;
                int col = pxBase + wn * 64 + nf * 8 + cQ;
                *(float2*)(d_v + (size_t)row * NPIX + col) =
                    make_float2(acc[mf][nf][0], acc[mf][nf][1]);
                *(float2*)(d_v + (size_t)(row + 8) * NPIX + col) =
                    make_float2(acc[mf][nf][2], acc[mf][nf][3]);
            }
        }
        return;
    }

    // ---- qk epilogue: fused g ----
    __syncthreads();                  // mainloop smem reads complete before reuse
    const int hp = wm >> 1;           // head pair slot: 0 or 1
    float* reg = exch + (hp * 2 + wn) * (32 * XPAD);

    if ((wm & 1) == 0) {
        // q warp: spill fragments as [channel][px] (channel = local row 0..31)
        #pragma unroll
        for (int mf = 0; mf < 2; mf++) {
            #pragma unroll
            for (int nf = 0; nf < 8; nf++) {
                int row = mf * 16 + rQ;
                int col = nf * 8 + cQ;
                *(float2*)(reg + row * XPAD + col) =
                    make_float2(acc[mf][nf][0], acc[mf][nf][1]);
                *(float2*)(reg + (row + 8) * XPAD + col) =
                    make_float2(acc[mf][nf][2], acc[mf][nf][3]);
            }
        }
    }
    __syncthreads();
    if (wm & 1) {
        // k warp: product with q, reduce 32 channels
        float ps[8][2];
        #pragma unroll
        for (int nf = 0; nf < 8; nf++) { ps[nf][0] = 0.f; ps[nf][1] = 0.f; }
        #pragma unroll
        for (int mf = 0; mf < 2; mf++) {
            #pragma unroll
            for (int nf = 0; nf < 8; nf++) {
                int row = mf * 16 + rQ;
                int col = nf * 8 + cQ;
                float2 q0 = *(const float2*)(reg + row * XPAD + col);
                float2 q1 = *(const float2*)(reg + (row + 8) * XPAD + col);
                ps[nf][0] += q0.x * acc[mf][nf][0] + q1.x * acc[mf][nf][2];
                ps[nf][1] += q0.y * acc[mf][nf][1] + q1.y * acc[mf][nf][3];
            }
        }
        #pragma unroll
        for (int nf = 0; nf < 8; nf++) {
            #pragma unroll
            for (int j = 0; j < 2; j++) {
                float v = ps[nf][j];
                v += __shfl_xor_sync(0xFFFFFFFFu, v, 4);
                v += __shfl_xor_sync(0xFFFFFFFFu, v, 8);
                v += __shfl_xor_sync(0xFFFFFFFFu, v, 16);
                ps[nf][j] = v;
            }
        }
        if (lane < 4) {
            const int head = y * 2 + hp;
            float* gp = d_g + (size_t)head * NPIX + pxBase + wn * 64;
            #pragma unroll
            for (int nf = 0; nf < 8; nf++) {
                *(float2*)(gp + nf * 8 + lane * 2) =
                    make_float2(ps[nf][0] * (1.0f / 16.0f),
                                ps[nf][1] * (1.0f / 16.0f));
            }
        }
    }
}

// ---------------------------------------------------------------------------
// Kernel E: softmax + weighted gather (R8 proven).
// 256 threads = 64 pixel-quads x 4 channel-groups (8 channels each).
// ---------------------------------------------------------------------------
__global__ __launch_bounds__(256) void attn_kernel(float* __restrict__ out)
{
    const int t    = threadIdx.x;
    const int cg   = t >> 6;
    const int quad = blockIdx.x * 64 + (t & 63);
    const int hd   = blockIdx.y;
    const int p4   = quad * 4;
    const int yy0  = p4 / HDIM;
    const int x4   = p4 - yy0 * HDIM;

    bool rok[3];
    int  roff[3];
    const bool lok  = (x4 > 0);
    const bool rokc = (x4 + 4 < HDIM);

    float win[3][6];
    #pragma unroll
    for (int r = 0; r < 3; r++) {
        int yy = yy0 + r - 1;
        rok[r]  = ((unsigned)yy < (unsigned)HDIM);
        roff[r] = yy * HDIM + x4;
        if (rok[r]) {
            const float* gp = d_g + (size_t)hd * NPIX + roff[r];
            win[r][0] = lok ? gp[-1] : 0.f;
            float4 m4 = *(const float4*)gp;
            win[r][1] = m4.x; win[r][2] = m4.y; win[r][3] = m4.z; win[r][4] = m4.w;
            win[r][5] = rokc ? gp[4] : 0.f;
        } else {
            #pragma unroll
            for (int i = 0; i < 6; i++) win[r][i] = 0.f;
        }
    }

    float wt[9][4];
    #pragma unroll
    for (int px = 0; px < 4; px++) {
        float l[9];
        float m = -1e30f;
        #pragma unroll
        for (int r = 0; r < 3; r++)
            #pragma unroll
            for (int j = 0; j < 3; j++) {
                float v = win[r][px + j];
                l[r * 3 + j] = v;
                m = fmaxf(m, v);
            }
        float z = 0.f;
        #pragma unroll
        for (int s = 0; s < 9; s++) {
            float e = __expf(l[s] - m);
            wt[s][px] = e;
            z += e;
        }
        float inv = __fdividef(1.f, z);
        #pragma unroll
        for (int s = 0; s < 9; s++) wt[s][px] *= inv;
    }

    const float* vbase = d_v + (size_t)(hd * 32 + cg * 8) * NPIX;
    float* obase       = out + (size_t)(hd * 32 + cg * 8) * NPIX;

    #pragma unroll
    for (int c = 0; c < 8; c++) {
        const float* vr = vbase + (size_t)c * NPIX;
        float a0 = 0.f, a1 = 0.f, a2 = 0.f, a3 = 0.f;
        #pragma unroll
        for (int r = 0; r < 3; r++) {
            float vw[6];
            if (rok[r]) {
                const float* vp = vr + roff[r];
                vw[0] = lok ? vp[-1] : 0.f;
                float4 m4 = *(const float4*)vp;
                vw[1] = m4.x; vw[2] = m4.y; vw[3] = m4.z; vw[4] = m4.w;
                vw[5] = rokc ? vp[4] : 0.f;
            } else {
                #pragma unroll
                for (int i = 0; i < 6; i++) vw[i] = 0.f;
            }
            #pragma unroll
            for (int j = 0; j < 3; j++) {
                const int s = r * 3 + j;
                a0 += wt[s][0] * vw[0 + j];
                a1 += wt[s][1] * vw[1 + j];
                a2 += wt[s][2] * vw[2 + j];
                a3 += wt[s][3] * vw[3 + j];
            }
        }
        *(float4*)(obase + (size_t)c * NPIX + p4) = make_float4(a0, a1, a2, a3);
    }
}

// ---------------------------------------------------------------------------
extern "C" void kernel_launch(void* const* d_in, const int* in_sizes, int n_in,
                              void* d_out, int out_size)
{
    const float* x  = (const float*)d_in[0];
    const float* wq = (const float*)d_in[1];
    const float* wk = (const float*)d_in[2];
    const float* wv = (const float*)d_in[3];
    float* out = (float*)d_out;

    wsplit_kernel<<<768 * C_IN / 256, 256>>>(wq, wk, wv);
    xsplit_kernel<<<NPIX / 32, 256>>>(x);
    mma_proj_kernel<<<dim3(NPIX / 128, 6), 256>>>();
    attn_kernel<<<dim3(NPIX / 4 / 64, NHEAD), 256>>>(out);
}